// round 1
// baseline (speedup 1.0000x reference)
#include <cuda_runtime.h>
#include <math.h>

// Problem constants
#define BB   2
#define SS   2048
#define HH   1024
#define NHH  16
#define HDD  64
#define MM   (BB*SS)      // 4096 rows
#define KK   1024         // reduction dim for projections

// Scratch (device globals; allocation inside kernel_launch is forbidden)
__device__ float g_q[BB*NHH*SS*HDD];
__device__ float g_k[BB*NHH*SS*HDD];
__device__ float g_v[BB*NHH*SS*HDD];
__device__ float g_attn[BB*NHH*SS*HDD];

// ---------------------------------------------------------------------------
// Kernel 1: fused QKV projection (+bias, +RoPE for q/k)
// grid (MM/64, NHH); block 256 (16x16 threads, 4x4 register tile)
// which: 0=q(rope) 1=k(rope) 2=v(no rope)
// ---------------------------------------------------------------------------
__global__ __launch_bounds__(256) void qkv_kernel(
    const float* __restrict__ A,     // hidden [MM, KK]
    const float* __restrict__ W,     // [KK, HH]
    const float* __restrict__ bias,  // [HH]
    int which)
{
    __shared__ float As[16][64];
    __shared__ float Ws[16][64];
    __shared__ float Cs[64][65];

    float* out = (which == 0) ? g_q : (which == 1) ? g_k : g_v;

    const int m0   = blockIdx.x * 64;
    const int head = blockIdx.y;
    const int n0   = head * 64;
    const int tid  = threadIdx.x;
    const int tx   = tid & 15;
    const int ty   = tid >> 4;

    float acc[4][4] = {};

    for (int k0 = 0; k0 < KK; k0 += 16) {
        #pragma unroll
        for (int i = 0; i < 4; i++) {
            int idx = tid + i * 256;          // 0..1023
            int r  = idx >> 4;
            int kk = idx & 15;
            As[kk][r] = A[(m0 + r) * KK + k0 + kk];
        }
        #pragma unroll
        for (int i = 0; i < 4; i++) {
            int idx = tid + i * 256;
            int kk = idx >> 6;
            int c  = idx & 63;
            Ws[kk][c] = W[(k0 + kk) * HH + n0 + c];
        }
        __syncthreads();
        #pragma unroll
        for (int kk = 0; kk < 16; kk++) {
            float a[4], w[4];
            #pragma unroll
            for (int i = 0; i < 4; i++) a[i] = As[kk][ty * 4 + i];
            #pragma unroll
            for (int j = 0; j < 4; j++) w[j] = Ws[kk][tx * 4 + j];
            #pragma unroll
            for (int i = 0; i < 4; i++)
                #pragma unroll
                for (int j = 0; j < 4; j++)
                    acc[i][j] += a[i] * w[j];
        }
        __syncthreads();
    }

    // stage C (+bias) into shared so RoPE can pair columns d and d+32
    #pragma unroll
    for (int i = 0; i < 4; i++)
        #pragma unroll
        for (int j = 0; j < 4; j++)
            Cs[ty * 4 + i][tx * 4 + j] = acc[i][j] + bias[n0 + tx * 4 + j];
    __syncthreads();

    if (which != 2) {
        // RoPE: 64 rows x 32 pairs = 2048 pairs, 8 per thread
        #pragma unroll
        for (int it = 0; it < 8; it++) {
            int p = it * 256 + tid;
            int r = p >> 5;        // 0..63
            int j = p & 31;        // pair index 0..31
            int grow = m0 + r;
            int b = grow >> 11;    // / 2048
            int s = grow & 2047;
            // inv_freq = 10000^(-(2j)/64)
            float inv = expf(-((float)(2 * j) / 64.0f) * 9.210340371976184f);
            float ang = (float)s * inv;
            float c, sn;
            sincosf(ang, &sn, &c);
            float x1 = Cs[r][j];
            float x2 = Cs[r][j + 32];
            float* o = out + ((size_t)(b * NHH + head) * SS + s) * HDD;
            o[j]      = x1 * c - x2 * sn;
            o[j + 32] = x1 * sn + x2 * c;
        }
    } else {
        #pragma unroll
        for (int it = 0; it < 16; it++) {
            int p = it * 256 + tid;
            int r = p >> 6;
            int d = p & 63;
            int grow = m0 + r;
            int b = grow >> 11;
            int s = grow & 2047;
            out[((size_t)(b * NHH + head) * SS + s) * HDD + d] = Cs[r][d];
        }
    }
}

// ---------------------------------------------------------------------------
// Kernel 2: flash attention (causal), fp32, online softmax
// grid (SS/64, NHH, BB); block 256; dynamic smem ~67KB
// ---------------------------------------------------------------------------
__global__ __launch_bounds__(256) void attn_kernel()
{
    extern __shared__ float sm[];
    float* Qs  = sm;                   // 64*65
    float* Ks  = Qs + 64 * 65;         // 64*65
    float* Vs  = Ks + 64 * 65;         // 64*65
    float* Ss  = Vs + 64 * 65;         // 64*65
    float* s_m = Ss + 64 * 65;         // 64
    float* s_l = s_m + 64;             // 64
    float* s_a = s_l + 64;             // 64

    const int qt   = blockIdx.x;
    const int head = blockIdx.y;
    const int b    = blockIdx.z;
    const int tid  = threadIdx.x;
    const int tx   = tid & 15;
    const int ty   = tid >> 4;
    const size_t base = (size_t)(b * NHH + head) * SS * HDD;
    const int q0 = qt * 64;

    // load Q tile
    #pragma unroll
    for (int i = 0; i < 16; i++) {
        int idx = tid + i * 256;
        int r = idx >> 6;
        int d = idx & 63;
        Qs[r * 65 + d] = g_q[base + (size_t)(q0 + r) * HDD + d];
    }
    if (tid < 64) { s_m[tid] = -INFINITY; s_l[tid] = 0.0f; }

    float o[4][4] = {};
    __syncthreads();

    for (int kt = 0; kt <= qt; kt++) {
        const int k0 = kt * 64;
        #pragma unroll
        for (int i = 0; i < 16; i++) {
            int idx = tid + i * 256;
            int r = idx >> 6;
            int d = idx & 63;
            Ks[r * 65 + d] = g_k[base + (size_t)(k0 + r) * HDD + d];
            Vs[r * 65 + d] = g_v[base + (size_t)(k0 + r) * HDD + d];
        }
        __syncthreads();

        // S = (Q K^T) * 1/sqrt(64), with causal mask on diagonal tile
        float acc[4][4] = {};
        #pragma unroll
        for (int d = 0; d < 64; d++) {
            float a[4], kv[4];
            #pragma unroll
            for (int i = 0; i < 4; i++) a[i]  = Qs[(ty * 4 + i) * 65 + d];
            #pragma unroll
            for (int j = 0; j < 4; j++) kv[j] = Ks[(tx * 4 + j) * 65 + d];
            #pragma unroll
            for (int i = 0; i < 4; i++)
                #pragma unroll
                for (int j = 0; j < 4; j++)
                    acc[i][j] += a[i] * kv[j];
        }
        const bool diag = (kt == qt);
        #pragma unroll
        for (int i = 0; i < 4; i++)
            #pragma unroll
            for (int j = 0; j < 4; j++) {
                float sv = acc[i][j] * 0.125f;
                if (diag && (k0 + tx * 4 + j) > (q0 + ty * 4 + i)) sv = -1.0e9f;
                Ss[(ty * 4 + i) * 65 + tx * 4 + j] = sv;
            }
        __syncthreads();

        // per-row online softmax (threads 0..63, one row each)
        if (tid < 64) {
            float mt = -INFINITY;
            #pragma unroll 8
            for (int c = 0; c < 64; c++) mt = fmaxf(mt, Ss[tid * 65 + c]);
            float mold = s_m[tid];
            float mnew = fmaxf(mold, mt);
            float al   = __expf(fmaxf(mold - mnew, -80.0f));
            float sum  = 0.0f;
            #pragma unroll 8
            for (int c = 0; c < 64; c++) {
                float p = __expf(fmaxf(Ss[tid * 65 + c] - mnew, -80.0f));
                Ss[tid * 65 + c] = p;
                sum += p;
            }
            s_l[tid] = s_l[tid] * al + sum;
            s_m[tid] = mnew;
            s_a[tid] = al;
        }
        __syncthreads();

        // O = O*alpha + P @ V
        float al[4];
        #pragma unroll
        for (int i = 0; i < 4; i++) al[i] = s_a[ty * 4 + i];
        #pragma unroll
        for (int i = 0; i < 4; i++)
            #pragma unroll
            for (int j = 0; j < 4; j++)
                o[i][j] *= al[i];
        #pragma unroll
        for (int d = 0; d < 64; d++) {
            float p[4], vv[4];
            #pragma unroll
            for (int i = 0; i < 4; i++) p[i]  = Ss[(ty * 4 + i) * 65 + d];
            #pragma unroll
            for (int j = 0; j < 4; j++) vv[j] = Vs[d * 65 + tx * 4 + j];
            #pragma unroll
            for (int i = 0; i < 4; i++)
                #pragma unroll
                for (int j = 0; j < 4; j++)
                    o[i][j] += p[i] * vv[j];
        }
        __syncthreads();
    }

    float linv[4];
    #pragma unroll
    for (int i = 0; i < 4; i++) linv[i] = 1.0f / s_l[ty * 4 + i];
    #pragma unroll
    for (int i = 0; i < 4; i++)
        #pragma unroll
        for (int j = 0; j < 4; j++)
            g_attn[base + (size_t)(q0 + ty * 4 + i) * HDD + tx * 4 + j] =
                o[i][j] * linv[i];
}

// ---------------------------------------------------------------------------
// Kernel 3: output projection, reads attn in [B,NH,S,HD] layout
// grid (MM/64, HH/64); block 256
// ---------------------------------------------------------------------------
__global__ __launch_bounds__(256) void proj_kernel(
    const float* __restrict__ W,     // wo [1024, 1024]
    const float* __restrict__ bias,  // bo [1024]
    float* __restrict__ out)         // [MM, HH]
{
    __shared__ float As[16][64];
    __shared__ float Ws[16][64];

    const int m0  = blockIdx.x * 64;
    const int n0  = blockIdx.y * 64;
    const int tid = threadIdx.x;
    const int tx  = tid & 15;
    const int ty  = tid >> 4;

    float acc[4][4] = {};

    for (int k0 = 0; k0 < KK; k0 += 16) {
        #pragma unroll
        for (int i = 0; i < 4; i++) {
            int idx = tid + i * 256;
            int r  = idx >> 4;
            int kk = idx & 15;
            int k  = k0 + kk;
            int h  = k >> 6;
            int d  = k & 63;
            int grow = m0 + r;
            int b = grow >> 11;
            int s = grow & 2047;
            As[kk][r] = g_attn[((size_t)(b * NHH + h) * SS + s) * HDD + d];
        }
        #pragma unroll
        for (int i = 0; i < 4; i++) {
            int idx = tid + i * 256;
            int kk = idx >> 6;
            int c  = idx & 63;
            Ws[kk][c] = W[(k0 + kk) * HH + n0 + c];
        }
        __syncthreads();
        #pragma unroll
        for (int kk = 0; kk < 16; kk++) {
            float a[4], w[4];
            #pragma unroll
            for (int i = 0; i < 4; i++) a[i] = As[kk][ty * 4 + i];
            #pragma unroll
            for (int j = 0; j < 4; j++) w[j] = Ws[kk][tx * 4 + j];
            #pragma unroll
            for (int i = 0; i < 4; i++)
                #pragma unroll
                for (int j = 0; j < 4; j++)
                    acc[i][j] += a[i] * w[j];
        }
        __syncthreads();
    }

    #pragma unroll
    for (int i = 0; i < 4; i++)
        #pragma unroll
        for (int j = 0; j < 4; j++)
            out[(size_t)(m0 + ty * 4 + i) * HH + n0 + tx * 4 + j] =
                acc[i][j] + bias[n0 + tx * 4 + j];
}

// ---------------------------------------------------------------------------
extern "C" void kernel_launch(void* const* d_in, const int* in_sizes, int n_in,
                              void* d_out, int out_size)
{
    const float* hs = (const float*)d_in[0];
    // d_in[1] = attention_mask (fixed causal) -- handled analytically
    const float* wq = (const float*)d_in[2];
    const float* bq = (const float*)d_in[3];
    const float* wk = (const float*)d_in[4];
    const float* bk = (const float*)d_in[5];
    const float* wv = (const float*)d_in[6];
    const float* bv = (const float*)d_in[7];
    const float* wo = (const float*)d_in[8];
    const float* bo = (const float*)d_in[9];
    float* out = (float*)d_out;

    dim3 blk(256);

    qkv_kernel<<<dim3(MM / 64, NHH), blk>>>(hs, wq, bq, 0);
    qkv_kernel<<<dim3(MM / 64, NHH), blk>>>(hs, wk, bk, 1);
    qkv_kernel<<<dim3(MM / 64, NHH), blk>>>(hs, wv, bv, 2);

    size_t smem = (size_t)(4 * 64 * 65 + 3 * 64) * sizeof(float);  // ~67KB
    cudaFuncSetAttribute(attn_kernel,
                         cudaFuncAttributeMaxDynamicSharedMemorySize,
                         (int)smem);
    attn_kernel<<<dim3(SS / 64, NHH, BB), blk, smem>>>();

    proj_kernel<<<dim3(MM / 64, HH / 64), blk>>>(wo, bo, out);
}

// round 3
// speedup vs baseline: 4.0516x; 4.0516x over previous
#include <cuda_runtime.h>
#include <math.h>

// ---------------------------------------------------------------------------
// Problem constants
// ---------------------------------------------------------------------------
#define BB   2
#define SS   2048
#define HH   1024
#define NHH  16
#define HDD  64
#define MM   (BB*SS)      // 4096
#define KK   1024

// Scratch (device globals)
__device__ float g_q[BB*NHH*SS*HDD];
__device__ float g_k[BB*NHH*SS*HDD];
__device__ float g_v[BB*NHH*SS*HDD];
__device__ float g_attn[BB*NHH*SS*HDD];
__device__ float g_cost[SS*32];
__device__ float g_sint[SS*32];

// ---------------------------------------------------------------------------
// Helpers (portable sm_80+ features only — NO tcgen05, harness targets sm_103 base)
// ---------------------------------------------------------------------------
__device__ __forceinline__ unsigned f2tf(float x) {
    unsigned u;
    asm("cvt.rna.tf32.f32 %0, %1;" : "=r"(u) : "f"(x));
    return u;
}
__device__ __forceinline__ float f2tf_f(float x) { return __uint_as_float(f2tf(x)); }

__device__ __forceinline__ void mma_tf32(float& c0, float& c1, float& c2, float& c3,
                                         unsigned a0, unsigned a1, unsigned a2, unsigned a3,
                                         unsigned b0, unsigned b1) {
    asm volatile(
        "mma.sync.aligned.m16n8k8.row.col.f32.tf32.tf32.f32 "
        "{%0,%1,%2,%3}, {%4,%5,%6,%7}, {%8,%9}, {%0,%1,%2,%3};"
        : "+f"(c0), "+f"(c1), "+f"(c2), "+f"(c3)
        : "r"(a0), "r"(a1), "r"(a2), "r"(a3), "r"(b0), "r"(b1));
}

__device__ __forceinline__ unsigned smem_u32(const void* p) {
    unsigned a;
    asm("{ .reg .u64 t; cvta.to.shared.u64 t, %1; cvt.u32.u64 %0, t; }"
        : "=r"(a) : "l"(p));
    return a;
}
__device__ __forceinline__ void cp16(unsigned s, const void* g) {
    asm volatile("cp.async.ca.shared.global [%0], [%1], 16;" :: "r"(s), "l"(g));
}
#define CP_COMMIT() asm volatile("cp.async.commit_group;" ::: "memory")
#define CP_WAIT0()  asm volatile("cp.async.wait_group 0;" ::: "memory")

// ---------------------------------------------------------------------------
// RoPE table
// ---------------------------------------------------------------------------
__global__ void rope_table_kernel() {
    int i = blockIdx.x * blockDim.x + threadIdx.x;
    int s = i >> 5, j = i & 31;
    float inv = expf(-((float)(2 * j) / 64.0f) * 9.210340371976184f);
    float ang = (float)s * inv;
    float c, sn;
    sincosf(ang, &sn, &c);
    g_cost[s * 32 + j] = c;
    g_sint[s * 32 + j] = sn;
}

// ---------------------------------------------------------------------------
// tf32 mma.sync GEMM, 128x128 CTA tile, 8 warps x (64x32)
// smem strides: A 36 (banks 4g+j), B 136 (banks 8j+g), C 132
// ---------------------------------------------------------------------------
#define AST 36
#define BST 136
#define CST 132
#define BUF_FLOATS (128*AST + 32*BST)          // 4608 + 4352 = 8960
#define GEMM_SMEM  (2 * BUF_FLOATS * 4)        // 71680 B; Cs (67584 B) reuses it

// which: 0=q(rope) 1=k(rope) 2=v
__global__ __launch_bounds__(256) void qkv_mma(
    const float* __restrict__ A,
    const float* __restrict__ wq, const float* __restrict__ wk, const float* __restrict__ wv,
    const float* __restrict__ bq, const float* __restrict__ bk, const float* __restrict__ bv)
{
    extern __shared__ float sm[];
    const int which = blockIdx.z;
    const float* W    = (which == 0) ? wq : (which == 1) ? wk : wv;
    const float* bias = (which == 0) ? bq : (which == 1) ? bk : bv;
    float* out        = (which == 0) ? g_q : (which == 1) ? g_k : g_v;

    const int n0 = blockIdx.x * 128, m0 = blockIdx.y * 128;
    const int tid = threadIdx.x, wid = tid >> 5, lane = tid & 31;
    const int g = lane >> 2, j = lane & 3;
    const int wm = wid & 1, wn = wid >> 1;

    float acc[4][4][4] = {};

    for (int c = 0; c < 32; c++) {
        const int k0 = c * 32;
        float* As = sm + (c & 1) * BUF_FLOATS;
        float* Bs = As + 128 * AST;

        #pragma unroll
        for (int i = 0; i < 4; i++) {
            int idx = tid + i * 256;
            int r = idx >> 3, c4 = idx & 7;
            float4 v = *(const float4*)&A[(size_t)(m0 + r) * KK + k0 + c4 * 4];
            float* d = As + r * AST + c4 * 4;
            d[0] = f2tf_f(v.x); d[1] = f2tf_f(v.y); d[2] = f2tf_f(v.z); d[3] = f2tf_f(v.w);
        }
        #pragma unroll
        for (int i = 0; i < 4; i++) {
            int idx = tid + i * 256;
            int kk = idx >> 5, n4 = idx & 31;
            float4 v = *(const float4*)&W[(size_t)(k0 + kk) * HH + n0 + n4 * 4];
            float4 o = make_float4(f2tf_f(v.x), f2tf_f(v.y), f2tf_f(v.z), f2tf_f(v.w));
            *(float4*)(Bs + kk * BST + n4 * 4) = o;
        }
        __syncthreads();

        #pragma unroll
        for (int kk2 = 0; kk2 < 4; kk2++) {
            unsigned a[4][4], bf[4][2];
            #pragma unroll
            for (int mt = 0; mt < 4; mt++) {
                int rb = (wm * 64 + mt * 16 + g) * AST + kk2 * 8 + j;
                a[mt][0] = __float_as_uint(As[rb]);
                a[mt][1] = __float_as_uint(As[rb + 8 * AST]);
                a[mt][2] = __float_as_uint(As[rb + 4]);
                a[mt][3] = __float_as_uint(As[rb + 8 * AST + 4]);
            }
            #pragma unroll
            for (int nt = 0; nt < 4; nt++) {
                int bb = (kk2 * 8 + j) * BST + wn * 32 + nt * 8 + g;
                bf[nt][0] = __float_as_uint(Bs[bb]);
                bf[nt][1] = __float_as_uint(Bs[bb + 4 * BST]);
            }
            #pragma unroll
            for (int mt = 0; mt < 4; mt++)
                #pragma unroll
                for (int nt = 0; nt < 4; nt++)
                    mma_tf32(acc[mt][nt][0], acc[mt][nt][1], acc[mt][nt][2], acc[mt][nt][3],
                             a[mt][0], a[mt][1], a[mt][2], a[mt][3],
                             bf[nt][0], bf[nt][1]);
        }
    }
    __syncthreads();

    float* Cs = sm;
    #pragma unroll
    for (int mt = 0; mt < 4; mt++)
        #pragma unroll
        for (int nt = 0; nt < 4; nt++) {
            int r = wm * 64 + mt * 16 + g, cc = wn * 32 + nt * 8 + 2 * j;
            *(float2*)&Cs[r * CST + cc]       = make_float2(acc[mt][nt][0], acc[mt][nt][1]);
            *(float2*)&Cs[(r + 8) * CST + cc] = make_float2(acc[mt][nt][2], acc[mt][nt][3]);
        }
    __syncthreads();

    if (which != 2) {
        #pragma unroll
        for (int it = 0; it < 32; it++) {
            int p = it * 256 + tid;      // 0..8191
            int r = p >> 6;
            int hh = (p >> 5) & 1;
            int jj = p & 31;
            int m = m0 + r, bb = m >> 11, s = m & 2047;
            int head = (n0 >> 6) + hh;
            float x1 = Cs[r * CST + hh * 64 + jj]      + bias[head * 64 + jj];
            float x2 = Cs[r * CST + hh * 64 + jj + 32] + bias[head * 64 + jj + 32];
            float cs = g_cost[s * 32 + jj], sn = g_sint[s * 32 + jj];
            float* op = out + ((size_t)(bb * NHH + head) * SS + s) * HDD;
            op[jj]      = x1 * cs - x2 * sn;
            op[jj + 32] = x1 * sn + x2 * cs;
        }
    } else {
        #pragma unroll
        for (int it = 0; it < 64; it++) {
            int p = it * 256 + tid;      // 0..16383
            int r = p >> 7, cc = p & 127;
            int m = m0 + r, bb = m >> 11, s = m & 2047;
            int head = (n0 >> 6) + (cc >> 6), d = cc & 63;
            out[((size_t)(bb * NHH + head) * SS + s) * HDD + d] =
                Cs[r * CST + cc] + bias[(n0 + cc)];
        }
    }
}

__global__ __launch_bounds__(256) void proj_mma(
    const float* __restrict__ W, const float* __restrict__ bo, float* __restrict__ outp)
{
    extern __shared__ float sm[];
    const int n0 = blockIdx.x * 128, m0 = blockIdx.y * 128;
    const int tid = threadIdx.x, wid = tid >> 5, lane = tid & 31;
    const int g = lane >> 2, j = lane & 3;
    const int wm = wid & 1, wn = wid >> 1;

    float acc[4][4][4] = {};

    for (int c = 0; c < 32; c++) {
        const int k0 = c * 32;
        const int h = k0 >> 6, dbase = k0 & 63;
        float* As = sm + (c & 1) * BUF_FLOATS;
        float* Bs = As + 128 * AST;

        #pragma unroll
        for (int i = 0; i < 4; i++) {
            int idx = tid + i * 256;
            int r = idx >> 3, c4 = idx & 7;
            int m = m0 + r, bb = m >> 11, s = m & 2047;
            float4 v = *(const float4*)&g_attn[((size_t)(bb * NHH + h) * SS + s) * HDD + dbase + c4 * 4];
            float* d = As + r * AST + c4 * 4;
            d[0] = f2tf_f(v.x); d[1] = f2tf_f(v.y); d[2] = f2tf_f(v.z); d[3] = f2tf_f(v.w);
        }
        #pragma unroll
        for (int i = 0; i < 4; i++) {
            int idx = tid + i * 256;
            int kk = idx >> 5, n4 = idx & 31;
            float4 v = *(const float4*)&W[(size_t)(k0 + kk) * HH + n0 + n4 * 4];
            float4 o = make_float4(f2tf_f(v.x), f2tf_f(v.y), f2tf_f(v.z), f2tf_f(v.w));
            *(float4*)(Bs + kk * BST + n4 * 4) = o;
        }
        __syncthreads();

        #pragma unroll
        for (int kk2 = 0; kk2 < 4; kk2++) {
            unsigned a[4][4], bf[4][2];
            #pragma unroll
            for (int mt = 0; mt < 4; mt++) {
                int rb = (wm * 64 + mt * 16 + g) * AST + kk2 * 8 + j;
                a[mt][0] = __float_as_uint(As[rb]);
                a[mt][1] = __float_as_uint(As[rb + 8 * AST]);
                a[mt][2] = __float_as_uint(As[rb + 4]);
                a[mt][3] = __float_as_uint(As[rb + 8 * AST + 4]);
            }
            #pragma unroll
            for (int nt = 0; nt < 4; nt++) {
                int bb = (kk2 * 8 + j) * BST + wn * 32 + nt * 8 + g;
                bf[nt][0] = __float_as_uint(Bs[bb]);
                bf[nt][1] = __float_as_uint(Bs[bb + 4 * BST]);
            }
            #pragma unroll
            for (int mt = 0; mt < 4; mt++)
                #pragma unroll
                for (int nt = 0; nt < 4; nt++)
                    mma_tf32(acc[mt][nt][0], acc[mt][nt][1], acc[mt][nt][2], acc[mt][nt][3],
                             a[mt][0], a[mt][1], a[mt][2], a[mt][3],
                             bf[nt][0], bf[nt][1]);
        }
    }
    __syncthreads();

    float* Cs = sm;
    #pragma unroll
    for (int mt = 0; mt < 4; mt++)
        #pragma unroll
        for (int nt = 0; nt < 4; nt++) {
            int r = wm * 64 + mt * 16 + g, cc = wn * 32 + nt * 8 + 2 * j;
            *(float2*)&Cs[r * CST + cc]       = make_float2(acc[mt][nt][0], acc[mt][nt][1]);
            *(float2*)&Cs[(r + 8) * CST + cc] = make_float2(acc[mt][nt][2], acc[mt][nt][3]);
        }
    __syncthreads();

    #pragma unroll
    for (int i = 0; i < 16; i++) {
        int idx = tid + i * 256;        // 4096 float4s
        int r = idx >> 5, c4 = idx & 31;
        float4 v = *(float4*)&Cs[r * CST + c4 * 4];
        float4 bv = *(const float4*)&bo[n0 + c4 * 4];
        v.x += bv.x; v.y += bv.y; v.z += bv.z; v.w += bv.w;
        *(float4*)&outp[(size_t)(m0 + r) * HH + n0 + c4 * 4] = v;
    }
}

// ---------------------------------------------------------------------------
// Flash attention with tf32 mma.sync; 64x64 tiles, 4 warps, cp.async K/V
// strides: Q/K/P 68 (banks 4g+j), V 72 (banks 8j+g)
// ---------------------------------------------------------------------------
#define QST 68
#define VST 72
#define ATTN_SMEM ((4352 + 2*4352 + 2*4608 + 4352 + 192) * 4)   // 107264 B

__global__ __launch_bounds__(128) void attn_kernel()
{
    extern __shared__ float sm[];
    float* Qs  = sm;                 // 64*68
    float* Ks  = Qs + 4352;          // 2 x 64*68
    float* Vs  = Ks + 2 * 4352;      // 2 x 64*72
    float* Ps  = Vs + 2 * 4608;      // 64*68
    float* s_m = Ps + 4352;
    float* s_l = s_m + 64;
    float* s_a = s_l + 64;

    const int qt = blockIdx.x, head = blockIdx.y, b = blockIdx.z;
    const int tid = threadIdx.x, wid = tid >> 5, lane = tid & 31;
    const int g = lane >> 2, j = lane & 3;
    const int r0 = wid * 16;
    const size_t base = (size_t)(b * NHH + head) * SS * HDD;
    const int q0 = qt * 64;

    const unsigned ks_base = smem_u32(Ks), vs_base = smem_u32(Vs);

    // Q load (+tf32 round)
    #pragma unroll
    for (int i = 0; i < 8; i++) {
        int idx = tid + i * 128;
        int r = idx >> 4, c4 = idx & 15;
        float4 v = *(const float4*)&g_q[base + (size_t)(q0 + r) * HDD + c4 * 4];
        float4 o = make_float4(f2tf_f(v.x), f2tf_f(v.y), f2tf_f(v.z), f2tf_f(v.w));
        *(float4*)&Qs[r * QST + c4 * 4] = o;
    }
    if (tid < 64) { s_m[tid] = -INFINITY; s_l[tid] = 0.0f; }

    // prefetch tile 0
    #pragma unroll
    for (int i = 0; i < 8; i++) {
        int idx = tid + i * 128;
        int r = idx >> 4, c4 = idx & 15;
        cp16(ks_base + (r * QST + c4 * 4) * 4, &g_k[base + (size_t)r * HDD + c4 * 4]);
        cp16(vs_base + (r * VST + c4 * 4) * 4, &g_v[base + (size_t)r * HDD + c4 * 4]);
    }
    CP_COMMIT();

    float o0[8] = {}, o1[8] = {}, o2[8] = {}, o3[8] = {};

    for (int kt = 0; kt <= qt; kt++) {
        const int bf = kt & 1;
        CP_WAIT0();
        __syncthreads();

        if (kt < qt) {
            const int nb = bf ^ 1;
            const int k0n = (kt + 1) * 64;
            #pragma unroll
            for (int i = 0; i < 8; i++) {
                int idx = tid + i * 128;
                int r = idx >> 4, c4 = idx & 15;
                cp16(ks_base + (nb * 4352 + r * QST + c4 * 4) * 4,
                     &g_k[base + (size_t)(k0n + r) * HDD + c4 * 4]);
                cp16(vs_base + (nb * 4608 + r * VST + c4 * 4) * 4,
                     &g_v[base + (size_t)(k0n + r) * HDD + c4 * 4]);
            }
            CP_COMMIT();
        }
        const float* Kb = Ks + bf * 4352;
        const float* Vb = Vs + bf * 4608;

        // S = Q K^T
        float s0[8] = {}, s1[8] = {}, s2[8] = {}, s3[8] = {};
        #pragma unroll
        for (int kk = 0; kk < 8; kk++) {
            int ab = (r0 + g) * QST + kk * 8 + j;
            unsigned a0 = __float_as_uint(Qs[ab]);
            unsigned a1 = __float_as_uint(Qs[ab + 8 * QST]);
            unsigned a2 = __float_as_uint(Qs[ab + 4]);
            unsigned a3 = __float_as_uint(Qs[ab + 8 * QST + 4]);
            #pragma unroll
            for (int nt = 0; nt < 8; nt++) {
                int bb2 = (nt * 8 + g) * QST + kk * 8 + j;
                unsigned b0 = __float_as_uint(Kb[bb2]);
                unsigned b1 = __float_as_uint(Kb[bb2 + 4]);
                mma_tf32(s0[nt], s1[nt], s2[nt], s3[nt], a0, a1, a2, a3, b0, b1);
            }
        }

        const bool diag = (kt == qt);
        #pragma unroll
        for (int nt = 0; nt < 8; nt++) {
            int col = nt * 8 + 2 * j;
            int rA = r0 + g, rB = r0 + g + 8;
            float v0 = s0[nt] * 0.125f, v1 = s1[nt] * 0.125f;
            float v2 = s2[nt] * 0.125f, v3 = s3[nt] * 0.125f;
            if (diag) {
                if (col     > rA) v0 = -1.0e9f;
                if (col + 1 > rA) v1 = -1.0e9f;
                if (col     > rB) v2 = -1.0e9f;
                if (col + 1 > rB) v3 = -1.0e9f;
            }
            *(float2*)&Ps[rA * QST + col] = make_float2(v0, v1);
            *(float2*)&Ps[rB * QST + col] = make_float2(v2, v3);
        }
        __syncthreads();

        // online softmax: 2 threads per row
        {
            int r = tid >> 1, hf = tid & 1;
            float* prow = Ps + r * QST + hf * 32;
            float mt = -INFINITY;
            #pragma unroll
            for (int c4 = 0; c4 < 8; c4++) {
                float4 v = *(float4*)&prow[c4 * 4];
                mt = fmaxf(mt, fmaxf(fmaxf(v.x, v.y), fmaxf(v.z, v.w)));
            }
            mt = fmaxf(mt, __shfl_xor_sync(0xffffffffu, mt, 1));
            float mold = s_m[r];
            float mnew = fmaxf(mold, mt);
            float sum = 0.0f;
            #pragma unroll
            for (int c4 = 0; c4 < 8; c4++) {
                float4 v = *(float4*)&prow[c4 * 4];
                float p0 = __expf(v.x - mnew), p1 = __expf(v.y - mnew);
                float p2 = __expf(v.z - mnew), p3 = __expf(v.w - mnew);
                sum += (p0 + p1) + (p2 + p3);
                *(float4*)&prow[c4 * 4] =
                    make_float4(f2tf_f(p0), f2tf_f(p1), f2tf_f(p2), f2tf_f(p3));
            }
            sum += __shfl_xor_sync(0xffffffffu, sum, 1);
            if (hf == 0) {
                float al = __expf(mold - mnew);
                s_a[r] = al;
                s_l[r] = s_l[r] * al + sum;
                s_m[r] = mnew;
            }
        }
        __syncthreads();

        // O = O*alpha + P @ V
        {
            float alA = s_a[r0 + g], alB = s_a[r0 + g + 8];
            #pragma unroll
            for (int nt = 0; nt < 8; nt++) {
                o0[nt] *= alA; o1[nt] *= alA;
                o2[nt] *= alB; o3[nt] *= alB;
            }
        }
        #pragma unroll
        for (int kk = 0; kk < 8; kk++) {
            int ab = (r0 + g) * QST + kk * 8 + j;
            unsigned a0 = __float_as_uint(Ps[ab]);
            unsigned a1 = __float_as_uint(Ps[ab + 8 * QST]);
            unsigned a2 = __float_as_uint(Ps[ab + 4]);
            unsigned a3 = __float_as_uint(Ps[ab + 8 * QST + 4]);
            #pragma unroll
            for (int nt = 0; nt < 8; nt++) {
                int bb2 = (kk * 8 + j) * VST + nt * 8 + g;
                unsigned b0 = __float_as_uint(Vb[bb2]);
                unsigned b1 = __float_as_uint(Vb[bb2 + 4 * VST]);
                mma_tf32(o0[nt], o1[nt], o2[nt], o3[nt], a0, a1, a2, a3, b0, b1);
            }
        }
    }

    {
        float liA = 1.0f / s_l[r0 + g], liB = 1.0f / s_l[r0 + g + 8];
        #pragma unroll
        for (int nt = 0; nt < 8; nt++) {
            int col = nt * 8 + 2 * j;
            *(float2*)&g_attn[base + (size_t)(q0 + r0 + g) * HDD + col] =
                make_float2(o0[nt] * liA, o1[nt] * liA);
            *(float2*)&g_attn[base + (size_t)(q0 + r0 + g + 8) * HDD + col] =
                make_float2(o2[nt] * liB, o3[nt] * liB);
        }
    }
}

// ---------------------------------------------------------------------------
extern "C" void kernel_launch(void* const* d_in, const int* in_sizes, int n_in,
                              void* d_out, int out_size)
{
    const float* hs = (const float*)d_in[0];
    // d_in[1] = attention_mask (fixed causal) -- handled analytically
    const float* wq = (const float*)d_in[2];
    const float* bq = (const float*)d_in[3];
    const float* wk = (const float*)d_in[4];
    const float* bk = (const float*)d_in[5];
    const float* wv = (const float*)d_in[6];
    const float* bv = (const float*)d_in[7];
    const float* wo = (const float*)d_in[8];
    const float* bo = (const float*)d_in[9];
    float* out = (float*)d_out;

    rope_table_kernel<<<SS * 32 / 256, 256>>>();

    cudaFuncSetAttribute(qkv_mma, cudaFuncAttributeMaxDynamicSharedMemorySize, GEMM_SMEM);
    cudaFuncSetAttribute(proj_mma, cudaFuncAttributeMaxDynamicSharedMemorySize, GEMM_SMEM);
    cudaFuncSetAttribute(attn_kernel, cudaFuncAttributeMaxDynamicSharedMemorySize, ATTN_SMEM);

    qkv_mma<<<dim3(8, 32, 3), 256, GEMM_SMEM>>>(hs, wq, wk, wv, bq, bk, bv);
    attn_kernel<<<dim3(SS / 64, NHH, BB), 128, ATTN_SMEM>>>();
    proj_mma<<<dim3(8, 32), 256, GEMM_SMEM>>>(wo, bo, out);
}